// round 8
// baseline (speedup 1.0000x reference)
#include <cuda_runtime.h>
#include <cuda_bf16.h>
#include <math.h>

// Sobel 3x3 (zero padding) + fused magnitude. No shared memory.
//
// R7 vs R6: occupancy push. ROWS 4 -> 2 (4 front-batched LDG.128/thread),
// register state trimmed (cache only the horizontal-diff q; smooth term p is
// used exactly once per output row when ROWS=2, so it's computed inline).
// __launch_bounds__(256,5) -> 40 warps/SM. Vertical re-reads (2x) are L2 hits;
// unique DRAM traffic unchanged (64 MB in + 64 MB out).
//  - sqrt.approx.f32, folded 0.25 scale, Y-edge template specialization,
//    evict-first output stores retained.

#define H 512
#define W 512
#define ROWS 2
#define NR (ROWS + 2)

__device__ __forceinline__ float sqrt_approx(float x) {
    float r;
    asm("sqrt.approx.f32 %0, %1;" : "=f"(r) : "f"(x));
    return r;
}

template<bool YEDGE>
__device__ __forceinline__ void sobel_strip(const float* __restrict__ src,
                                            float* __restrict__ dst,
                                            int lane, int c0, int r0,
                                            bool haveL, bool haveR) {
    // ---- Front-batched loads: 4 independent LDG.128 (+ lane-edge scalars) ----
    float4 v[NR];
    float  el[NR], er[NR];

    #pragma unroll
    for (int r = 0; r < NR; r++) {
        const int gr = r0 - 1 + r;
        el[r] = 0.f; er[r] = 0.f;
        if (!YEDGE || (unsigned)gr < (unsigned)H) {
            const float* __restrict__ row = src + gr * W;
            v[r] = *reinterpret_cast<const float4*>(row + c0);
            if (lane == 0  && haveL) el[r] = row[c0 - 1];
            if (lane == 31 && haveR) er[r] = row[c0 + 4];
        } else {
            v[r] = make_float4(0.f, 0.f, 0.f, 0.f);
        }
    }

    // ---- Halo resolve via shuffle (warp-uniform control flow) ----
    float lh[NR], rh[NR];
    #pragma unroll
    for (int r = 0; r < NR; r++) {
        const float sl = __shfl_up_sync(0xffffffffu, v[r].w, 1);
        const float sr = __shfl_down_sync(0xffffffffu, v[r].x, 1);
        lh[r] = (lane == 0)  ? el[r] : sl;
        rh[r] = (lane == 31) ? er[r] : sr;
    }

    // ---- Cache horizontal diff q (reused across output rows) ----
    // q[r][i] = t[i] - t[i+2] over the 6-wide window {lh, v.x..v.w, rh}
    float q[NR][4];
    #pragma unroll
    for (int r = 0; r < NR; r++) {
        q[r][0] = lh[r]  - v[r].y;
        q[r][1] = v[r].x - v[r].z;
        q[r][2] = v[r].y - v[r].w;
        q[r][3] = v[r].z - rh[r];
    }

    // ---- Output rows: gy needs p = horizontal smooth of top & bottom rows,
    //      each used exactly once -> compute inline.
    #pragma unroll
    for (int j = 0; j < ROWS; j++) {
        const int rt = j, rb = j + 2;

        const float tt[6] = { lh[rt], v[rt].x, v[rt].y, v[rt].z, v[rt].w, rh[rt] };
        const float bb[6] = { lh[rb], v[rb].x, v[rb].y, v[rb].z, v[rb].w, rh[rb] };

        float4 o;
        float* op = &o.x;
        #pragma unroll
        for (int i = 0; i < 4; i++) {
            const float gx = fmaf(2.f, q[j + 1][i], q[j][i] + q[j + 2][i]);
            const float pt = fmaf(2.f, tt[i + 1], tt[i] + tt[i + 2]);
            const float pb = fmaf(2.f, bb[i + 1], bb[i] + bb[i + 2]);
            const float gy = pt - pb;
            const float m  = fmaf(gx, gx, fmaf(gy, gy, 1.6e-3f));
            op[i] = 0.25f * sqrt_approx(m);
        }
        __stcs(reinterpret_cast<float4*>(dst + (size_t)(r0 + j) * W + c0), o);
    }
}

__global__ __launch_bounds__(256, 5)
void sobel_kernel(const float* __restrict__ in, float* __restrict__ out) {
    const int lane = threadIdx.x;                 // 0..31
    const int wy   = threadIdx.y;                 // 0..7
    const int img  = blockIdx.z;
    const int c0   = blockIdx.x * 128 + lane * 4;
    const int r0   = (blockIdx.y * 8 + wy) * ROWS;

    const float* __restrict__ src = in  + (size_t)img * (H * W);
    float* __restrict__       dst = out + (size_t)img * (H * W);

    const bool haveL = (c0 > 0);
    const bool haveR = (c0 + 4 < W);

    // r0 is warp-uniform; only strips touching row 0 or row H-1 need checks.
    if (r0 != 0 && r0 + ROWS != H) {
        sobel_strip<false>(src, dst, lane, c0, r0, haveL, haveR);
    } else {
        sobel_strip<true>(src, dst, lane, c0, r0, haveL, haveR);
    }
}

extern "C" void kernel_launch(void* const* d_in, const int* in_sizes, int n_in,
                              void* d_out, int out_size) {
    (void)in_sizes; (void)n_in; (void)out_size;
    const float* x = (const float*)d_in[0];
    float* y = (float*)d_out;

    dim3 block(32, 8, 1);                      // 256 threads
    dim3 grid(W / 128, H / (8 * ROWS), 64);    // (4, 32, 64) = 8192 blocks
    sobel_kernel<<<grid, block>>>(x, y);
}